// round 12
// baseline (speedup 1.0000x reference)
#include <cuda_runtime.h>
#include <cuda_bf16.h>
#include <math.h>

#define B   64
#define S   128
#define D   64
#define H   256
#define P   1024
#define VR  32000
#define G4  1024
#define THRESH 0.64f

typedef unsigned long long ull;

__device__ float    g_xt  [2*S*B*D];
__device__ float    g_xg  [2*S*B*G4];
__device__ float    g_hs  [2*S*B*H];
__device__ float    g_hbuf[2*2*B*H];
__device__ float    g_cat [B*2*H];
__device__ float    g_h1  [B*P];
__device__ float    g_h2  [B*P];
__device__ float    g_hbn [B*P];
__device__ int      g_cnt [B];

__device__ __forceinline__ ull pk2(float lo, float hi) {
    ull r; asm("mov.b64 %0, {%1, %2};" : "=l"(r) : "f"(lo), "f"(hi)); return r;
}
__device__ __forceinline__ float2 upk2(ull v) {
    float2 f; asm("mov.b64 {%0, %1}, %2;" : "=f"(f.x), "=f"(f.y) : "l"(v)); return f;
}
__device__ __forceinline__ ull ffma2(ull a, ull b, ull c) {
    ull d; asm("fma.rn.f32x2 %0, %1, %2, %3;" : "=l"(d) : "l"(a), "l"(b), "l"(c)); return d;
}
__device__ __forceinline__ float fast_tanh(float x) {
    float r; asm("tanh.approx.f32 %0, %1;" : "=f"(r) : "f"(x)); return r;
}
__device__ __forceinline__ float sigf(float x) {
    return fmaf(fast_tanh(0.5f * x), 0.5f, 0.5f);
}

__global__ void init_kernel() {
    int t = threadIdx.x;
    if (t < B)  g_cnt[t] = 0;
}

__global__ void finalize_kernel(float* out_tail, int do_write) {
    int b = threadIdx.x;
    if (b < B && do_write) {
        int n = g_cnt[b];
        if (n < 1) n = 1;
        out_tail[b] = (float)n;
    }
}

__global__ void prep_x(const float* __restrict__ x1, const float* __restrict__ x2) {
    int idx = blockIdx.x * blockDim.x + threadIdx.x;
    if (idx >= 2*S*B*D) return;
    int d   = idx & 63;
    int b   = (idx >> 6) & 63;
    int s   = (idx >> 12) & 127;
    int inp = idx >> 19;
    const float* x = inp ? x2 : x1;
    g_xt[idx] = x[(b * S + s) * D + d];
}

// MODE 0: bias(+bias2); 1: exact GELU; 2: resid + relu; 3: relu + count(v>THRESH)
template<int MODE>
__global__ void gemm_k(const float* __restrict__ A, const float* __restrict__ W,
                       const float* __restrict__ bias, const float* __restrict__ bias2,
                       const float* __restrict__ resid, float* __restrict__ C,
                       int M, int N, int K, int* __restrict__ cnt) {
    __shared__ float As[16][64];
    __shared__ float Bs[16][64];
    __shared__ int   scnt[64];

    const int t     = threadIdx.x;
    const int mBase = blockIdx.y * 64;
    const int nBase = blockIdx.x * 64;
    const int lr    = t >> 2;
    const int lk    = (t & 3) * 4;
    const int tm    = t >> 4;
    const int tn    = t & 15;

    if (MODE == 3 && t < 64) scnt[t] = 0;

    ull accP[2][4];
    #pragma unroll
    for (int i = 0; i < 2; i++)
        #pragma unroll
        for (int j = 0; j < 4; j++) accP[i][j] = 0ull;

    for (int kb = 0; kb < K; kb += 16) {
        __syncthreads();
        float4 av = *(const float4*)(A + (size_t)(mBase + lr) * K + kb + lk);
        float4 wv = *(const float4*)(W + (size_t)(nBase + lr) * K + kb + lk);
        As[lk + 0][lr] = av.x; As[lk + 1][lr] = av.y; As[lk + 2][lr] = av.z; As[lk + 3][lr] = av.w;
        Bs[lk + 0][lr] = wv.x; Bs[lk + 1][lr] = wv.y; Bs[lk + 2][lr] = wv.z; Bs[lk + 3][lr] = wv.w;
        __syncthreads();
        #pragma unroll
        for (int k = 0; k < 16; k++) {
            float4 a = *(const float4*)&As[k][tm * 4];
            float4 b = *(const float4*)&Bs[k][tn * 4];
            ull aP0 = pk2(a.x, a.y);
            ull aP1 = pk2(a.z, a.w);
            ull b0  = pk2(b.x, b.x);
            ull b1  = pk2(b.y, b.y);
            ull b2  = pk2(b.z, b.z);
            ull b3  = pk2(b.w, b.w);
            accP[0][0] = ffma2(aP0, b0, accP[0][0]);
            accP[0][1] = ffma2(aP0, b1, accP[0][1]);
            accP[0][2] = ffma2(aP0, b2, accP[0][2]);
            accP[0][3] = ffma2(aP0, b3, accP[0][3]);
            accP[1][0] = ffma2(aP1, b0, accP[1][0]);
            accP[1][1] = ffma2(aP1, b1, accP[1][1]);
            accP[1][2] = ffma2(aP1, b2, accP[1][2]);
            accP[1][3] = ffma2(aP1, b3, accP[1][3]);
        }
    }

    float acc[4][4];
    #pragma unroll
    for (int p = 0; p < 2; p++)
        #pragma unroll
        for (int j = 0; j < 4; j++) {
            float2 v = upk2(accP[p][j]);
            acc[2*p][j]   = v.x;
            acc[2*p+1][j] = v.y;
        }

    #pragma unroll
    for (int i = 0; i < 4; i++) {
        int r  = mBase + tm * 4 + i;
        int rc = 0;
        #pragma unroll
        for (int jj = 0; jj < 4; jj++) {
            int n = nBase + tn * 4 + jj;
            float v = acc[i][jj] + bias[n];
            if (bias2) v += bias2[n];
            if (MODE == 1) v = 0.5f * v * (1.f + erff(v * 0.70710678118654752f));
            if (MODE == 2) v = resid[(size_t)r * N + n] + fmaxf(v, 0.f);
            if (MODE == 3) { v = fmaxf(v, 0.f); if (v > THRESH) rc++; }
            C[(size_t)r * N + n] = v;
        }
        if (MODE == 3 && rc) atomicAdd(&scnt[tm * 4 + i], rc);
    }
    if (MODE == 3) {
        __syncthreads();
        if (t < 64 && scnt[t]) atomicAdd(&cnt[mBase + t], scnt[t]);
    }
}

// ================= persistent LSTM scan v3: cluster-8 + shuffle reduction =================
// grid 128 = inp(2) x bc(8: 8 batch rows) x hc(8: 32 j). cluster (8,1,1) = one (inp,bc) group.
// block 512: warp w = jjpair (16 warps, jj = 2w+jj_lo); lane = jj_lo(bit4), kq(bits2-3), rs(bits0-1).
// Each thread: 4 gates x 2 rows (rs*2, rs*2+1) over k2-chunk [kq*32, kq*32+32).
// SMEM: wk 128KB (bank-tuned), hd 8704B (k-paired h, bank-tuned), mbarrier 8B.
#define SCAN3_WK_BYTES 131072
#define SCAN3_HD_BYTES 8704            // 32 kk * 272
#define SCAN3_SMEM (SCAN3_WK_BYTES + SCAN3_HD_BYTES + 16)

__device__ __forceinline__ void mbar_init(unsigned addr, unsigned count) {
    asm volatile("mbarrier.init.shared.b64 [%0], %1;" :: "r"(addr), "r"(count) : "memory");
}
__device__ __forceinline__ void mbar_arrive_cluster(unsigned addr, unsigned rank) {
    asm volatile(
        "{\n\t.reg .b32 remAddr;\n\t"
        "mapa.shared::cluster.u32 remAddr, %0, %1;\n\t"
        "mbarrier.arrive.shared::cluster.b64 _, [remAddr];\n\t}"
        :: "r"(addr), "r"(rank) : "memory");
}
__device__ __forceinline__ void mbar_wait_parity_cluster(unsigned addr, unsigned parity) {
    unsigned done;
    asm volatile(
        "{\n\t.reg .pred p;\n\t"
        "mbarrier.try_wait.parity.acquire.cluster.shared::cta.b64 p, [%1], %2;\n\t"
        "selp.b32 %0, 1, 0, p;\n\t}"
        : "=r"(done) : "r"(addr), "r"(parity) : "memory");
    if (!done) {
        asm volatile(
            "{\n\t.reg .pred P1;\n\t"
            "WAIT_LOOP_%=: \n\t"
            "mbarrier.try_wait.parity.acquire.cluster.shared::cta.b64 P1, [%0], %1, 0x989680;\n\t"
            "@P1 bra.uni WAIT_DONE_%=;\n\t"
            "bra.uni WAIT_LOOP_%=;\n\t"
            "WAIT_DONE_%=: \n\t}"
            :: "r"(addr), "r"(parity) : "memory");
    }
}

__global__ __launch_bounds__(512, 1) __cluster_dims__(8, 1, 1)
void lstm_scan3(const float* __restrict__ xg, const float* __restrict__ Whh,
                float* __restrict__ hs_out, float* __restrict__ cat_out) {
    extern __shared__ unsigned char smraw[];
    ull*           wk = (ull*)smraw;                       // bank-tuned weight layout
    unsigned char* hd = smraw + SCAN3_WK_BYTES;            // bank-tuned h layout
    unsigned mbar;
    {
        unsigned sb;
        asm("{ .reg .u64 tmp; cvta.to.shared.u64 tmp, %1; cvt.u32.u64 %0, tmp; }"
            : "=r"(sb) : "l"(smraw));
        mbar = sb + SCAN3_WK_BYTES + SCAN3_HD_BYTES;
    }

    const int t     = threadIdx.x;                 // 512
    const int w     = t >> 5;                      // jjpair 0..15
    const int lane  = t & 31;
    const int jj_lo = lane >> 4;                   // 0..1
    const int kq    = (lane >> 2) & 3;             // 0..3
    const int rs    = lane & 3;                    // 0..3 -> rows rs*2, rs*2+1
    const int jj    = w * 2 + jj_lo;               // 0..31

    const int bx   = blockIdx.x;                   // 0..127
    const int inp  = bx >> 6;
    const int bc   = (bx >> 3) & 7;
    const int hc   = bx & 7;                       // = cluster rank
    const int b0   = bc * 8;
    const int jge  = hc * 32 + jj;

    // ---- fill weights ----
    // layout: off(k2,jj,g) = kk*4096 + jjpair*256 + (g>>1)*128 + (jj_lo + 2*kq)*16 + (g&1)*8
    //   (kk = k2 & 31, kq = k2 >> 5)
    for (int i = t; i < 128 * 32 * 4; i += 512) {
        int g   = i & 3;
        int j2  = (i >> 2) & 31;
        int k2  = i >> 7;
        int kk  = k2 & 31, kqe = k2 >> 5;
        int off = kk * 4096 + (j2 >> 1) * 256 + (g >> 1) * 128 + ((j2 & 1) + 2 * kqe) * 16 + (g & 1) * 8;
        wk[off >> 3] = *(const ull*)(Whh + ((size_t)(g * H + hc * 32 + j2)) * H + 2 * k2);
    }
    // ---- zero hd ----
    for (int i = t; i < SCAN3_HD_BYTES / 8; i += 512) ((ull*)hd)[i] = 0ull;

    // ---- mbarrier init + cluster sync ----
    if (t == 0) mbar_init(mbar, 8);
    __syncthreads();
    asm volatile("barrier.cluster.arrive.aligned;" ::: "memory");
    asm volatile("barrier.cluster.wait.aligned;"   ::: "memory");

    const bool active = (kq == 0);
    float c0 = 0.f, c1 = 0.f, sum0 = 0.f, sum1 = 0.f;
    const int row0 = rs * 2, row1 = rs * 2 + 1;

    // thread-local smem byte offsets
    const int woff0 = w * 256 + (jj_lo + 2 * kq) * 16;         // + kk*4096
    const int hoff0 = (rs * 4 + kq) * 16;                      // + kk*272

    for (int s = 0; s < S; s++) {
        // xg prefetch (active lanes only; consumed after k-loop)
        float xv[2][4];
        if (active) {
            #pragma unroll
            for (int r = 0; r < 2; r++) {
                const float* xr = xg + ((size_t)((inp * S + s) * B) + b0 + row0 + r) * G4;
                xv[r][0] = __ldcg(xr + jge);
                xv[r][1] = __ldcg(xr + H + jge);
                xv[r][2] = __ldcg(xr + 2 * H + jge);
                xv[r][3] = __ldcg(xr + 3 * H + jge);
            }
        }

        // ---- k-loop: 32 k2 per thread, 8 FFMA2 each ----
        ull ai0 = 0, ai1 = 0, af0 = 0, af1 = 0, ag0 = 0, ag1 = 0, ao0 = 0, ao1 = 0;
        const unsigned char* wp = (const unsigned char*)wk + woff0;
        const unsigned char* hp = hd + hoff0;
        #pragma unroll 4
        for (int kk = 0; kk < 32; kk++) {
            ulonglong2 w01 = *(const ulonglong2*)(wp);         // (w_i, w_f) k-paired
            ulonglong2 w23 = *(const ulonglong2*)(wp + 128);   // (w_g, w_o)
            ulonglong2 hh  = *(const ulonglong2*)(hp);         // (row0, row1) k-paired
            ai0 = ffma2(w01.x, hh.x, ai0);  ai1 = ffma2(w01.x, hh.y, ai1);
            af0 = ffma2(w01.y, hh.x, af0);  af1 = ffma2(w01.y, hh.y, af1);
            ag0 = ffma2(w23.x, hh.x, ag0);  ag1 = ffma2(w23.x, hh.y, ag1);
            ao0 = ffma2(w23.y, hh.x, ao0);  ao1 = ffma2(w23.y, hh.y, ao1);
            wp += 4096;
            hp += 272;
        }

        // ---- butterfly reduce over kq (lane bits 2,3) ----
        #pragma unroll
        for (int mask = 4; mask <= 8; mask <<= 1) {
            ai0 = ffma2(0, 0, ai0); // no-op spacing not needed; keep plain adds below
            float2 tmp;
            // 64-bit shuffles
            ull v;
            v = __shfl_xor_sync(0xffffffffu, ai0, mask); { tmp = upk2(v); float2 a = upk2(ai0); ai0 = pk2(a.x + tmp.x, a.y + tmp.y); }
            v = __shfl_xor_sync(0xffffffffu, ai1, mask); { tmp = upk2(v); float2 a = upk2(ai1); ai1 = pk2(a.x + tmp.x, a.y + tmp.y); }
            v = __shfl_xor_sync(0xffffffffu, af0, mask); { tmp = upk2(v); float2 a = upk2(af0); af0 = pk2(a.x + tmp.x, a.y + tmp.y); }
            v = __shfl_xor_sync(0xffffffffu, af1, mask); { tmp = upk2(v); float2 a = upk2(af1); af1 = pk2(a.x + tmp.x, a.y + tmp.y); }
            v = __shfl_xor_sync(0xffffffffu, ag0, mask); { tmp = upk2(v); float2 a = upk2(ag0); ag0 = pk2(a.x + tmp.x, a.y + tmp.y); }
            v = __shfl_xor_sync(0xffffffffu, ag1, mask); { tmp = upk2(v); float2 a = upk2(ag1); ag1 = pk2(a.x + tmp.x, a.y + tmp.y); }
            v = __shfl_xor_sync(0xffffffffu, ao0, mask); { tmp = upk2(v); float2 a = upk2(ao0); ao0 = pk2(a.x + tmp.x, a.y + tmp.y); }
            v = __shfl_xor_sync(0xffffffffu, ao1, mask); { tmp = upk2(v); float2 a = upk2(ao1); ao1 = pk2(a.x + tmp.x, a.y + tmp.y); }
        }

        // ---- epilogue on active lanes (kq==0): 2 rows each ----
        if (active) {
            float2 vi0 = upk2(ai0), vf0 = upk2(af0), vg0 = upk2(ag0), vo0 = upk2(ao0);
            float gi = vi0.x + vi0.y + xv[0][0];
            float gf = vf0.x + vf0.y + xv[0][1];
            float gg = vg0.x + vg0.y + xv[0][2];
            float go = vo0.x + vo0.y + xv[0][3];
            c0 = sigf(gf) * c0 + sigf(gi) * fast_tanh(gg);
            float h0 = sigf(go) * fast_tanh(c0);

            float2 vi1 = upk2(ai1), vf1 = upk2(af1), vg1 = upk2(ag1), vo1 = upk2(ao1);
            gi = vi1.x + vi1.y + xv[1][0];
            gf = vf1.x + vf1.y + xv[1][1];
            gg = vg1.x + vg1.y + xv[1][2];
            go = vo1.x + vo1.y + xv[1][3];
            c1 = sigf(gf) * c1 + sigf(gi) * fast_tanh(gg);
            float h1 = sigf(go) * fast_tanh(c1);

            float* hw = g_hbuf + ((size_t)((inp * 2 + (s & 1)) * B) + b0) * H;
            __stcg(hw + (size_t)row0 * H + jge, h0);
            __stcg(hw + (size_t)row1 * H + jge, h1);

            if (hs_out) {
                float* ho = hs_out + ((size_t)((inp * S + s) * B) + b0) * H;
                ho[(size_t)row0 * H + jge] = h0;
                ho[(size_t)row1 * H + jge] = h1;
            } else {
                sum0 += h0; sum1 += h1;
            }
        }

        // ---- publish + cluster barrier ----
        __syncthreads();                     // all STGs issued & ordered before arrive
        if (t < 8) mbar_arrive_cluster(mbar, (unsigned)t);
        mbar_wait_parity_cluster(mbar, (unsigned)(s & 1));

        // ---- reload 8 rows x 256 h from L2 into bank-tuned k-paired layout ----
        {
            const float* hb = g_hbuf + ((size_t)((inp * 2 + (s & 1)) * B) + b0) * H;
            int r  = t >> 6;                 // 0..7
            int q4 = t & 63;                 // float4 index in row
            float4 v = __ldcg((const float4*)(hb + (size_t)r * H) + q4);
            int k2a = 2 * q4;                // covers k 4q4..4q4+1
            int kk  = k2a & 31, kqe = k2a >> 5;
            int rsw = r >> 1, rlo = r & 1;
            unsigned char* d0 = hd + kk * 272 + (rsw * 4 + kqe) * 16 + rlo * 8;
            *(ull*)d0         = pk2(v.x, v.y);          // k2a
            *(ull*)(d0 + 272) = pk2(v.z, v.w);          // k2a+1 (kk+1, same kq)
        }
        __syncthreads();
    }

    if (cat_out && active) {
        cat_out[(b0 + row0) * (2 * H) + inp * H + jge] = sum0;
        cat_out[(b0 + row1) * (2 * H) + inp * H + jge] = sum1;
    }

    asm volatile("barrier.cluster.arrive.aligned;" ::: "memory");
    asm volatile("barrier.cluster.wait.aligned;"   ::: "memory");
}

__global__ void bn_kernel(const float* __restrict__ h, const float* __restrict__ gam,
                          const float* __restrict__ bet, float* __restrict__ out) {
    int c = blockIdx.x * blockDim.x + threadIdx.x;
    if (c >= P) return;
    float s = 0.f, s2 = 0.f;
    for (int r = 0; r < B; r++) {
        float v = h[r * P + c];
        s += v; s2 += v * v;
    }
    float mu  = s * (1.f / B);
    float var = s2 * (1.f / B) - mu * mu;
    float inv = rsqrtf(var + 1e-5f) * gam[c];
    float bb  = bet[c];
    for (int r = 0; r < B; r++) {
        out[r * P + c] = (h[r * P + c] - mu) * inv + bb;
    }
}

extern "C" void kernel_launch(void* const* d_in, const int* in_sizes, int n_in,
                              void* d_out, int out_size) {
    const float* x1    = (const float*)d_in[0];
    const float* x2    = (const float*)d_in[1];
    const float* Wih0  = (const float*)d_in[2];
    const float* Whh0  = (const float*)d_in[3];
    const float* bih0  = (const float*)d_in[4];
    const float* bhh0  = (const float*)d_in[5];
    const float* Wih1  = (const float*)d_in[6];
    const float* Whh1  = (const float*)d_in[7];
    const float* bih1  = (const float*)d_in[8];
    const float* bhh1  = (const float*)d_in[9];
    const float* fc1_w = (const float*)d_in[10];
    const float* fc1_b = (const float*)d_in[11];
    const float* fc2_w = (const float*)d_in[12];
    const float* fc2_b = (const float*)d_in[13];
    const float* fc3_w = (const float*)d_in[14];
    const float* fc3_b = (const float*)d_in[15];
    const float* bn_g  = (const float*)d_in[16];
    const float* bn_b  = (const float*)d_in[17];
    float* out = (float*)d_out;

    float *p_xt, *p_xg, *p_hs, *p_cat, *p_h1, *p_h2, *p_hbn;
    int   *p_cnt;
    cudaGetSymbolAddress((void**)&p_xt,  g_xt);
    cudaGetSymbolAddress((void**)&p_xg,  g_xg);
    cudaGetSymbolAddress((void**)&p_hs,  g_hs);
    cudaGetSymbolAddress((void**)&p_cat, g_cat);
    cudaGetSymbolAddress((void**)&p_h1,  g_h1);
    cudaGetSymbolAddress((void**)&p_h2,  g_h2);
    cudaGetSymbolAddress((void**)&p_hbn, g_hbn);
    cudaGetSymbolAddress((void**)&p_cnt, g_cnt);

    cudaFuncSetAttribute(lstm_scan3, cudaFuncAttributeMaxDynamicSharedMemorySize, SCAN3_SMEM);

    init_kernel<<<1, 128>>>();
    prep_x<<<(2*S*B*D + 255) / 256, 256>>>(x1, x2);

    // xg0 = xT @ Wih0^T + (bih0+bhh0)
    gemm_k<0><<<dim3(G4/64, (2*S*B)/64), 256>>>(p_xt, Wih0, bih0, bhh0, nullptr, p_xg,
                                                2*S*B, G4, D, nullptr);
    // layer-0 recurrence
    lstm_scan3<<<128, 512, SCAN3_SMEM>>>(p_xg, Whh0, p_hs, nullptr);

    // xg1 = hs @ Wih1^T + (bih1+bhh1)
    gemm_k<0><<<dim3(G4/64, (2*S*B)/64), 256>>>(p_hs, Wih1, bih1, bhh1, nullptr, p_xg,
                                                2*S*B, G4, H, nullptr);
    // layer-1 recurrence (time-sum into concat)
    lstm_scan3<<<128, 512, SCAN3_SMEM>>>(p_xg, Whh1, nullptr, p_cat);

    // fc1 + GELU
    gemm_k<1><<<dim3(P/64, 1), 256>>>(p_cat, fc1_w, fc1_b, nullptr, nullptr, p_h1,
                                      B, P, 2*H, nullptr);
    // fc2 + relu + residual
    gemm_k<2><<<dim3(P/64, 1), 256>>>(p_h1, fc2_w, fc2_b, nullptr, p_h1, p_h2,
                                      B, P, P, nullptr);
    // batchnorm
    bn_kernel<<<(P + 255) / 256, 256>>>(p_h2, bn_g, bn_b, p_hbn);
    // fc3 + relu + count
    gemm_k<3><<<dim3(VR/64, 1), 256>>>(p_hbn, fc3_w, fc3_b, nullptr, nullptr, out,
                                       B, VR, P, p_cnt);

    int has_tail = (out_size >= B * VR + B) ? 1 : 0;
    finalize_kernel<<<1, 64>>>(out + (size_t)B * VR, has_tail);
}

// round 15
// speedup vs baseline: 1.4136x; 1.4136x over previous
#include <cuda_runtime.h>
#include <cuda_bf16.h>
#include <math.h>

#define B   64
#define S   128
#define D   64
#define H   256
#define P   1024
#define VR  32000
#define G4  1024
#define THRESH 0.64f

typedef unsigned long long ull;

__device__ float    g_xt  [2*S*B*D];
__device__ float    g_xg  [2*S*B*G4];
__device__ float    g_hs  [2*S*B*H];
__device__ float    g_hbuf[2*2*B*H];
__device__ float    g_cat [B*2*H];
__device__ float    g_h1  [B*P];
__device__ float    g_h2  [B*P];
__device__ float    g_hbn [B*P];
__device__ int      g_cnt [B];
__device__ unsigned g_bar [16];

__device__ __forceinline__ ull pk2(float lo, float hi) {
    ull r; asm("mov.b64 %0, {%1, %2};" : "=l"(r) : "f"(lo), "f"(hi)); return r;
}
__device__ __forceinline__ float2 upk2(ull v) {
    float2 f; asm("mov.b64 {%0, %1}, %2;" : "=f"(f.x), "=f"(f.y) : "l"(v)); return f;
}
__device__ __forceinline__ ull ffma2(ull a, ull b, ull c) {
    ull d; asm("fma.rn.f32x2 %0, %1, %2, %3;" : "=l"(d) : "l"(a), "l"(b), "l"(c)); return d;
}
__device__ __forceinline__ ull add2(ull a, ull b) {
    ull d; asm("add.rn.f32x2 %0, %1, %2;" : "=l"(d) : "l"(a), "l"(b)); return d;
}
__device__ __forceinline__ float fast_tanh(float x) {
    float r; asm("tanh.approx.f32 %0, %1;" : "=f"(r) : "f"(x)); return r;
}
__device__ __forceinline__ float sigf(float x) {
    return fmaf(fast_tanh(0.5f * x), 0.5f, 0.5f);
}

__global__ void init_kernel() {
    int t = threadIdx.x;
    if (t < 16) g_bar[t] = 0u;
    if (t < B)  g_cnt[t] = 0;
}

__global__ void finalize_kernel(float* out_tail, int do_write) {
    int b = threadIdx.x;
    if (b < B && do_write) {
        int n = g_cnt[b];
        if (n < 1) n = 1;
        out_tail[b] = (float)n;
    }
}

__global__ void prep_x(const float* __restrict__ x1, const float* __restrict__ x2) {
    int idx = blockIdx.x * blockDim.x + threadIdx.x;
    if (idx >= 2*S*B*D) return;
    int d   = idx & 63;
    int b   = (idx >> 6) & 63;
    int s   = (idx >> 12) & 127;
    int inp = idx >> 19;
    const float* x = inp ? x2 : x1;
    g_xt[idx] = x[(b * S + s) * D + d];
}

// MODE 0: bias(+bias2); 1: exact GELU; 2: resid + relu; 3: relu + count(v>THRESH)
template<int MODE>
__global__ void gemm_k(const float* __restrict__ A, const float* __restrict__ W,
                       const float* __restrict__ bias, const float* __restrict__ bias2,
                       const float* __restrict__ resid, float* __restrict__ C,
                       int M, int N, int K, int* __restrict__ cnt) {
    __shared__ float As[16][64];
    __shared__ float Bs[16][64];
    __shared__ int   scnt[64];

    const int t     = threadIdx.x;
    const int mBase = blockIdx.y * 64;
    const int nBase = blockIdx.x * 64;
    const int lr    = t >> 2;
    const int lk    = (t & 3) * 4;
    const int tm    = t >> 4;
    const int tn    = t & 15;

    if (MODE == 3 && t < 64) scnt[t] = 0;

    ull accP[2][4];
    #pragma unroll
    for (int i = 0; i < 2; i++)
        #pragma unroll
        for (int j = 0; j < 4; j++) accP[i][j] = 0ull;

    for (int kb = 0; kb < K; kb += 16) {
        __syncthreads();
        float4 av = *(const float4*)(A + (size_t)(mBase + lr) * K + kb + lk);
        float4 wv = *(const float4*)(W + (size_t)(nBase + lr) * K + kb + lk);
        As[lk + 0][lr] = av.x; As[lk + 1][lr] = av.y; As[lk + 2][lr] = av.z; As[lk + 3][lr] = av.w;
        Bs[lk + 0][lr] = wv.x; Bs[lk + 1][lr] = wv.y; Bs[lk + 2][lr] = wv.z; Bs[lk + 3][lr] = wv.w;
        __syncthreads();
        #pragma unroll
        for (int k = 0; k < 16; k++) {
            float4 a = *(const float4*)&As[k][tm * 4];
            float4 b = *(const float4*)&Bs[k][tn * 4];
            ull aP0 = pk2(a.x, a.y);
            ull aP1 = pk2(a.z, a.w);
            ull b0  = pk2(b.x, b.x);
            ull b1  = pk2(b.y, b.y);
            ull b2  = pk2(b.z, b.z);
            ull b3  = pk2(b.w, b.w);
            accP[0][0] = ffma2(aP0, b0, accP[0][0]);
            accP[0][1] = ffma2(aP0, b1, accP[0][1]);
            accP[0][2] = ffma2(aP0, b2, accP[0][2]);
            accP[0][3] = ffma2(aP0, b3, accP[0][3]);
            accP[1][0] = ffma2(aP1, b0, accP[1][0]);
            accP[1][1] = ffma2(aP1, b1, accP[1][1]);
            accP[1][2] = ffma2(aP1, b2, accP[1][2]);
            accP[1][3] = ffma2(aP1, b3, accP[1][3]);
        }
    }

    float acc[4][4];
    #pragma unroll
    for (int p = 0; p < 2; p++)
        #pragma unroll
        for (int j = 0; j < 4; j++) {
            float2 v = upk2(accP[p][j]);
            acc[2*p][j]   = v.x;
            acc[2*p+1][j] = v.y;
        }

    #pragma unroll
    for (int i = 0; i < 4; i++) {
        int r  = mBase + tm * 4 + i;
        int rc = 0;
        #pragma unroll
        for (int jj = 0; jj < 4; jj++) {
            int n = nBase + tn * 4 + jj;
            float v = acc[i][jj] + bias[n];
            if (bias2) v += bias2[n];
            if (MODE == 1) v = 0.5f * v * (1.f + erff(v * 0.70710678118654752f));
            if (MODE == 2) v = resid[(size_t)r * N + n] + fmaxf(v, 0.f);
            if (MODE == 3) { v = fmaxf(v, 0.f); if (v > THRESH) rc++; }
            C[(size_t)r * N + n] = v;
        }
        if (MODE == 3 && rc) atomicAdd(&scnt[tm * 4 + i], rc);
    }
    if (MODE == 3) {
        __syncthreads();
        if (t < 64 && scnt[t]) atomicAdd(&cnt[mBase + t], scnt[t]);
    }
}

// ========== persistent LSTM scan v4: scan2 grid/occupancy + in-warp shuffle reduction ==========
// grid 256 = inp(2) x bc(8: 8 batch rows) x hc(16: 16 j). group = 16 CTAs (inp,bc), L2 counter barrier.
// block 256 = 8 warps; warp w = j-pair (jj = 2w + jj_lo); lane = jj_lo(bit4) kq(bits2-3) rr(bits0-1).
// Thread: j = 2w+jj_lo, rows (2rr, 2rr+1), 4 gates, k2 in [kq*32, kq*32+32).
// SMEM: wk 64KB  off(kk,w,gh,jj_lo,kq,glo) = kk*2048 + w*256 + gh*128 + (jj_lo+2kq)*16 + glo*8
//       hd 8704B off(kk,rr,kq,half)        = kk*272 + (rr*4+kq)*16 + half*8
#define SCAN4_WK_BYTES 65536
#define SCAN4_HD_BYTES 8704
#define SCAN4_SMEM (SCAN4_WK_BYTES + SCAN4_HD_BYTES)

__global__ __launch_bounds__(256, 2)
void lstm_scan4(const float* __restrict__ xg, const float* __restrict__ Whh,
                float* __restrict__ hs_out, float* __restrict__ cat_out) {
    extern __shared__ unsigned char smraw[];
    ull*           wk = (ull*)smraw;
    unsigned char* hd = smraw + SCAN4_WK_BYTES;

    const int t     = threadIdx.x;                 // 256
    const int w     = t >> 5;                      // 0..7
    const int lane  = t & 31;
    const int jj_lo = lane >> 4;                   // 0..1
    const int kq    = (lane >> 2) & 3;             // 0..3
    const int rr    = lane & 3;                    // 0..3
    const int jj    = w * 2 + jj_lo;               // 0..15

    const int bx   = blockIdx.x;                   // 0..255
    const int inp  = bx >> 7;
    const int bc   = (bx >> 4) & 7;
    const int hc   = bx & 15;
    const int grp  = bx >> 4;                      // 0..15
    const int b0   = bc * 8;
    const int jge  = hc * 16 + jj;
    const int row0 = rr * 2, row1 = rr * 2 + 1;

    // ---- fill weights (8192 ull) ----
    for (int i = t; i < 128 * 16 * 4; i += 256) {
        int g   = i & 3;
        int j2  = (i >> 2) & 15;
        int k2  = i >> 6;
        int kk  = k2 & 31, kqe = k2 >> 5;
        int off = kk * 2048 + (j2 >> 1) * 256 + (g >> 1) * 128 + ((j2 & 1) + 2 * kqe) * 16 + (g & 1) * 8;
        wk[off >> 3] = *(const ull*)(Whh + ((size_t)(g * H + hc * 16 + j2)) * H + 2 * k2);
    }
    for (int i = t; i < SCAN4_HD_BYTES / 8; i += 256) ((ull*)hd)[i] = 0ull;
    __syncthreads();

    const bool active = (kq == 0);
    float c0 = 0.f, c1 = 0.f, sum0 = 0.f, sum1 = 0.f;

    const unsigned char* wp0 = (const unsigned char*)wk + w * 256 + (jj_lo + 2 * kq) * 16;
    const unsigned char* hp0 = hd + (rr * 4 + kq) * 16;

    for (int s = 0; s < S; s++) {
        // xg prefetch (active lanes; consumed after k-loop)
        float xv0a = 0.f, xv0b = 0.f, xv0c = 0.f, xv0d = 0.f;
        float xv1a = 0.f, xv1b = 0.f, xv1c = 0.f, xv1d = 0.f;
        if (active) {
            const float* xr0 = xg + ((size_t)((inp * S + s) * B) + b0 + row0) * G4;
            const float* xr1 = xg + ((size_t)((inp * S + s) * B) + b0 + row1) * G4;
            xv0a = __ldcg(xr0 + jge);        xv0b = __ldcg(xr0 + H + jge);
            xv0c = __ldcg(xr0 + 2*H + jge);  xv0d = __ldcg(xr0 + 3*H + jge);
            xv1a = __ldcg(xr1 + jge);        xv1b = __ldcg(xr1 + H + jge);
            xv1c = __ldcg(xr1 + 2*H + jge);  xv1d = __ldcg(xr1 + 3*H + jge);
        }

        // ---- k-loop: 32 k2 per thread ----
        ull ai0 = 0, ai1 = 0, af0 = 0, af1 = 0, ag0 = 0, ag1 = 0, ao0 = 0, ao1 = 0;
        const unsigned char* wp = wp0;
        const unsigned char* hp = hp0;
        #pragma unroll 8
        for (int kk = 0; kk < 32; kk++) {
            ulonglong2 wif = *(const ulonglong2*)(wp);         // (w_i, w_f) k-paired
            ulonglong2 wgo = *(const ulonglong2*)(wp + 128);   // (w_g, w_o)
            ulonglong2 hh  = *(const ulonglong2*)(hp);         // (h_row0, h_row1) k-paired
            ai0 = ffma2(wif.x, hh.x, ai0);  ai1 = ffma2(wif.x, hh.y, ai1);
            af0 = ffma2(wif.y, hh.x, af0);  af1 = ffma2(wif.y, hh.y, af1);
            ag0 = ffma2(wgo.x, hh.x, ag0);  ag1 = ffma2(wgo.x, hh.y, ag1);
            ao0 = ffma2(wgo.y, hh.x, ao0);  ao1 = ffma2(wgo.y, hh.y, ao1);
            wp += 2048;
            hp += 272;
        }

        // ---- butterfly reduction over kq (lane bits 2,3) ----
        #pragma unroll
        for (int mask = 4; mask <= 8; mask <<= 1) {
            ai0 = add2(ai0, __shfl_xor_sync(0xffffffffu, ai0, mask));
            ai1 = add2(ai1, __shfl_xor_sync(0xffffffffu, ai1, mask));
            af0 = add2(af0, __shfl_xor_sync(0xffffffffu, af0, mask));
            af1 = add2(af1, __shfl_xor_sync(0xffffffffu, af1, mask));
            ag0 = add2(ag0, __shfl_xor_sync(0xffffffffu, ag0, mask));
            ag1 = add2(ag1, __shfl_xor_sync(0xffffffffu, ag1, mask));
            ao0 = add2(ao0, __shfl_xor_sync(0xffffffffu, ao0, mask));
            ao1 = add2(ao1, __shfl_xor_sync(0xffffffffu, ao1, mask));
        }

        // ---- epilogue on active lanes (kq==0): rows row0,row1 ----
        if (active) {
            float2 vi = upk2(ai0), vf = upk2(af0), vg = upk2(ag0), vo = upk2(ao0);
            float gi = vi.x + vi.y + xv0a;
            float gf = vf.x + vf.y + xv0b;
            float gg = vg.x + vg.y + xv0c;
            float go = vo.x + vo.y + xv0d;
            c0 = sigf(gf) * c0 + sigf(gi) * fast_tanh(gg);
            float h0 = sigf(go) * fast_tanh(c0);

            vi = upk2(ai1); vf = upk2(af1); vg = upk2(ag1); vo = upk2(ao1);
            gi = vi.x + vi.y + xv1a;
            gf = vf.x + vf.y + xv1b;
            gg = vg.x + vg.y + xv1c;
            go = vo.x + vo.y + xv1d;
            c1 = sigf(gf) * c1 + sigf(gi) * fast_tanh(gg);
            float h1 = sigf(go) * fast_tanh(c1);

            float* hw = g_hbuf + ((size_t)((inp * 2 + (s & 1)) * B) + b0) * H;
            __stcg(hw + (size_t)row0 * H + jge, h0);
            __stcg(hw + (size_t)row1 * H + jge, h1);

            if (hs_out) {
                float* ho = hs_out + ((size_t)((inp * S + s) * B) + b0) * H;
                ho[(size_t)row0 * H + jge] = h0;
                ho[(size_t)row1 * H + jge] = h1;
            } else {
                sum0 += h0; sum1 += h1;
            }
        }

        // ---- group barrier (16 CTAs, L2 counter) ----
        __threadfence();
        __syncthreads();
        if (t == 0) {
            atomicAdd(&g_bar[grp], 1u);
            unsigned tgt = 16u * (unsigned)(s + 1);
            while (*(volatile unsigned*)&g_bar[grp] < tgt) { }
            __threadfence();
        }
        __syncthreads();

        // ---- reload 8 rows x 256 h into k-paired layout ----
        {
            const float* hb = g_hbuf + ((size_t)((inp * 2 + (s & 1)) * B) + b0) * H;
            int f  = t;                      // 0..255, plus second half below
            #pragma unroll
            for (int q = 0; q < 2; q++) {
                int r  = f >> 6;             // 0..7
                int q4 = f & 63;
                float4 v = __ldcg((const float4*)(hb + (size_t)r * H) + q4);
                int k2a = 2 * q4;
                int kk  = k2a & 31, kqe = k2a >> 5;
                int rre = r >> 1, half = r & 1;
                unsigned char* d0 = hd + kk * 272 + (rre * 4 + kqe) * 16 + half * 8;
                *(ull*)d0          = pk2(v.x, v.y);     // k2a
                *(ull*)(d0 + 272)  = pk2(v.z, v.w);     // k2a+1
                f += 256;
            }
        }
        __syncthreads();
    }

    if (cat_out && active) {
        cat_out[(b0 + row0) * (2 * H) + inp * H + jge] = sum0;
        cat_out[(b0 + row1) * (2 * H) + inp * H + jge] = sum1;
    }
}

__global__ void bn_kernel(const float* __restrict__ h, const float* __restrict__ gam,
                          const float* __restrict__ bet, float* __restrict__ out) {
    int c = blockIdx.x * blockDim.x + threadIdx.x;
    if (c >= P) return;
    float s = 0.f, s2 = 0.f;
    for (int r = 0; r < B; r++) {
        float v = h[r * P + c];
        s += v; s2 += v * v;
    }
    float mu  = s * (1.f / B);
    float var = s2 * (1.f / B) - mu * mu;
    float inv = rsqrtf(var + 1e-5f) * gam[c];
    float bb  = bet[c];
    for (int r = 0; r < B; r++) {
        out[r * P + c] = (h[r * P + c] - mu) * inv + bb;
    }
}

extern "C" void kernel_launch(void* const* d_in, const int* in_sizes, int n_in,
                              void* d_out, int out_size) {
    const float* x1    = (const float*)d_in[0];
    const float* x2    = (const float*)d_in[1];
    const float* Wih0  = (const float*)d_in[2];
    const float* Whh0  = (const float*)d_in[3];
    const float* bih0  = (const float*)d_in[4];
    const float* bhh0  = (const float*)d_in[5];
    const float* Wih1  = (const float*)d_in[6];
    const float* Whh1  = (const float*)d_in[7];
    const float* bih1  = (const float*)d_in[8];
    const float* bhh1  = (const float*)d_in[9];
    const float* fc1_w = (const float*)d_in[10];
    const float* fc1_b = (const float*)d_in[11];
    const float* fc2_w = (const float*)d_in[12];
    const float* fc2_b = (const float*)d_in[13];
    const float* fc3_w = (const float*)d_in[14];
    const float* fc3_b = (const float*)d_in[15];
    const float* bn_g  = (const float*)d_in[16];
    const float* bn_b  = (const float*)d_in[17];
    float* out = (float*)d_out;

    float *p_xt, *p_xg, *p_hs, *p_cat, *p_h1, *p_h2, *p_hbn;
    int   *p_cnt;
    cudaGetSymbolAddress((void**)&p_xt,  g_xt);
    cudaGetSymbolAddress((void**)&p_xg,  g_xg);
    cudaGetSymbolAddress((void**)&p_hs,  g_hs);
    cudaGetSymbolAddress((void**)&p_cat, g_cat);
    cudaGetSymbolAddress((void**)&p_h1,  g_h1);
    cudaGetSymbolAddress((void**)&p_h2,  g_h2);
    cudaGetSymbolAddress((void**)&p_hbn, g_hbn);
    cudaGetSymbolAddress((void**)&p_cnt, g_cnt);

    cudaFuncSetAttribute(lstm_scan4, cudaFuncAttributeMaxDynamicSharedMemorySize, SCAN4_SMEM);

    init_kernel<<<1, 128>>>();
    prep_x<<<(2*S*B*D + 255) / 256, 256>>>(x1, x2);

    // xg0 = xT @ Wih0^T + (bih0+bhh0)
    gemm_k<0><<<dim3(G4/64, (2*S*B)/64), 256>>>(p_xt, Wih0, bih0, bhh0, nullptr, p_xg,
                                                2*S*B, G4, D, nullptr);
    // layer-0 recurrence
    lstm_scan4<<<256, 256, SCAN4_SMEM>>>(p_xg, Whh0, p_hs, nullptr);

    init_kernel<<<1, 128>>>();

    // xg1 = hs @ Wih1^T + (bih1+bhh1)
    gemm_k<0><<<dim3(G4/64, (2*S*B)/64), 256>>>(p_hs, Wih1, bih1, bhh1, nullptr, p_xg,
                                                2*S*B, G4, H, nullptr);
    // layer-1 recurrence (time-sum into concat)
    lstm_scan4<<<256, 256, SCAN4_SMEM>>>(p_xg, Whh1, nullptr, p_cat);

    // fc1 + GELU
    gemm_k<1><<<dim3(P/64, 1), 256>>>(p_cat, fc1_w, fc1_b, nullptr, nullptr, p_h1,
                                      B, P, 2*H, nullptr);
    // fc2 + relu + residual
    gemm_k<2><<<dim3(P/64, 1), 256>>>(p_h1, fc2_w, fc2_b, nullptr, p_h1, p_h2,
                                      B, P, P, nullptr);
    // batchnorm
    bn_kernel<<<(P + 255) / 256, 256>>>(p_h2, bn_g, bn_b, p_hbn);
    // fc3 + relu + count
    gemm_k<3><<<dim3(VR/64, 1), 256>>>(p_hbn, fc3_w, fc3_b, nullptr, nullptr, out,
                                       B, VR, P, p_cnt);

    int has_tail = (out_size >= B * VR + B) ? 1 : 0;
    finalize_kernel<<<1, 64>>>(out + (size_t)B * VR, has_tail);
}